// round 15
// baseline (speedup 1.0000x reference)
#include <cuda_runtime.h>

// CostVolumeBidirectional: f1,f2 (8,96,96,320) f32 -> out (8,9,96,320) f32
// out[b][d][h][w] = (1/96) * sum_c f1[b][c][h][w] * f2[b][c][h][w-(d-4)]
// zero where w-(d-4) outside [0,320).
//
// R15: R10 (best: 45.8us, DRAM 53%) + register double-buffering. R10's warps
// eat full DRAM latency every channel because at 64 regs ptxas can't prefetch
// the next iteration's loads. Here channel c+1's four float4s are loaded into
// a ping-pong register set BEFORE the 36 FMAs of channel c, overlapping load
// latency with compute across the whole scheduler. Register budget raised to
// 85 via __launch_bounds__(128,6): 24 warps/SM instead of 26 (-7% occupancy)
// for ~1 full round of latency hiding per warp. R11-R14 established that any
// smem/shuffle halo transport costs more than these L2-hit redundant loads.

#define BS 8
#define FS 96
#define H  96
#define W  320
#define WQ (W / 4)      // 80 float4 groups per row
#define NP 9            // disparity planes

#define GROUPS 64       // float4-groups per block
#define CHUNKS 2        // channel chunks per group
#define CHP (FS / CHUNKS)  // 48 channels per thread
#define BLOCK (GROUPS * CHUNKS)   // 128 threads

__global__ __launch_bounds__(BLOCK, 6)
void cost_volume_kernel(const float* __restrict__ f1,
                        const float* __restrict__ f2,
                        float* __restrict__ out) {
    // partial accumulators: [chunk][group][plane] as float4 (4 columns)
    __shared__ float4 s[CHUNKS][GROUPS][NP];   // 18 KB

    const int tid = threadIdx.x;
    const int g   = tid & (GROUPS - 1);
    const int cc  = tid >> 6;

    const int t  = blockIdx.x * GROUPS + g;    // global float4-group id
    const int wq = t % WQ;
    const int bh = t / WQ;
    const int h  = bh % H;
    const int b  = bh / H;

    float acc[NP][4];
#pragma unroll
    for (int d = 0; d < NP; d++)
#pragma unroll
        for (int k = 0; k < 4; k++) acc[d][k] = 0.0f;

    const int cs = H * W;
    const size_t base = ((size_t)b * FS + cc * CHP) * cs + (size_t)h * W + (size_t)wq * 4;
    const float* q1 = f1 + base;
    const float* q2 = f2 + base;

    const bool hasL = (wq > 0);
    const bool hasR = (wq < WQ - 1);
    const float4 z4 = make_float4(0.f, 0.f, 0.f, 0.f);

    // ping-pong register sets for a/m/l/r
    float4 A[2], M[2], L[2], R[2];

    // preload channel 0 into set 0
    A[0] = *(const float4*)(q1);
    M[0] = *(const float4*)(q2);
    L[0] = hasL ? *(const float4*)(q2 - 4) : z4;
    R[0] = hasR ? *(const float4*)(q2 + 4) : z4;

#pragma unroll 2
    for (int c = 0; c < CHP; c++) {
        const int cur = c & 1;
        const int nxt = cur ^ 1;

        // prefetch channel c+1 BEFORE consuming channel c
        const float* n1 = q1 + cs;
        const float* n2 = q2 + cs;
        if (c + 1 < CHP) {
            A[nxt] = *(const float4*)(n1);
            M[nxt] = *(const float4*)(n2);
            L[nxt] = hasL ? *(const float4*)(n2 - 4) : z4;
            R[nxt] = hasR ? *(const float4*)(n2 + 4) : z4;
        }
        q1 = n1;
        q2 = n2;

        float w12[12] = {L[cur].x, L[cur].y, L[cur].z, L[cur].w,
                         M[cur].x, M[cur].y, M[cur].z, M[cur].w,
                         R[cur].x, R[cur].y, R[cur].z, R[cur].w};
        float av[4] = {A[cur].x, A[cur].y, A[cur].z, A[cur].w};

        // plane d => shift i = d-4; f2 window index = k + 8 - d
#pragma unroll
        for (int d = 0; d < NP; d++) {
#pragma unroll
            for (int k = 0; k < 4; k++) {
                acc[d][k] = fmaf(av[k], w12[k + 8 - d], acc[d][k]);
            }
        }
    }

    // stash partials
#pragma unroll
    for (int d = 0; d < NP; d++) {
        s[cc][g][d] = make_float4(acc[d][0], acc[d][1], acc[d][2], acc[d][3]);
    }
    __syncthreads();

    // reduce 2 chunks + write out: 64 groups x 9 planes = 576 float4 stores
    const float inv = 1.0f / (float)FS;
    for (int item = tid; item < GROUPS * NP; item += BLOCK) {
        const int g2 = item / NP;
        const int d  = item % NP;

        float4 a0 = s[0][g2][d];
        float4 a1 = s[1][g2][d];

        float4 o;
        o.x = (a0.x + a1.x) * inv;
        o.y = (a0.y + a1.y) * inv;
        o.z = (a0.z + a1.z) * inv;
        o.w = (a0.w + a1.w) * inv;

        const int t2  = blockIdx.x * GROUPS + g2;
        const int wq2 = t2 % WQ;
        const int bh2 = t2 / WQ;
        const int h2  = bh2 % H;
        const int b2  = bh2 / H;

        const size_t oidx = (((size_t)b2 * NP + d) * H + h2) * W + (size_t)wq2 * 4;
        *(float4*)(out + oidx) = o;
    }
}

extern "C" void kernel_launch(void* const* d_in, const int* in_sizes, int n_in,
                              void* d_out, int out_size) {
    const float* f1 = (const float*)d_in[0];
    const float* f2 = (const float*)d_in[1];
    float* out = (float*)d_out;

    const int total_groups = BS * H * WQ;          // 61440
    const int grid = total_groups / GROUPS;        // 960 blocks
    cost_volume_kernel<<<grid, BLOCK>>>(f1, f2, out);
}

// round 16
// speedup vs baseline: 1.4343x; 1.4343x over previous
#include <cuda_runtime.h>

// CostVolumeBidirectional: f1,f2 (8,96,96,320) f32 -> out (8,9,96,320) f32
// out[b][d][h][w] = (1/96) * sum_c f1[b][c][h][w] * f2[b][c][h][w-(d-4)]
// zero where w-(d-4) outside [0,320).
//
// R16: R10 byte-for-byte (best kernel: 45.8us, DRAM 53%) + L2 prefetch at
// distance 8 channels. R11-R15 all lost to R10's ptxas schedule; the model
// now says R10 is latency-bound through the L1tex queue (26 warps front-batch
// 16 LDG.128 each; queue inflates the ~600cyc DRAM miss latency; warps stall
// in lockstep). prefetch.global.L2 has no register writeback and no L1
// wavefront: it warms L2 ~1200cyc ahead so the real LDGs hit L2 (~250cyc)
// instead of DRAM, cutting the latency the queue multiplies. Halo lines are
// covered by neighboring threads' m-prefetches.

#define BS 8
#define FS 96
#define H  96
#define W  320
#define WQ (W / 4)      // 80 float4 groups per row
#define NP 9            // disparity planes

#define GROUPS 64       // float4-groups per block
#define CHUNKS 2        // channel chunks per group
#define CHP (FS / CHUNKS)  // 48 channels per thread
#define BLOCK (GROUPS * CHUNKS)   // 128 threads
#define PF 8            // prefetch distance in channels (2 unrolled bodies)

__device__ __forceinline__ void l2_prefetch(const float* p) {
    asm volatile("prefetch.global.L2 [%0];" :: "l"(p));
}

__global__ __launch_bounds__(BLOCK, 8)
void cost_volume_kernel(const float* __restrict__ f1,
                        const float* __restrict__ f2,
                        float* __restrict__ out) {
    // partial accumulators: [chunk][group][plane] as float4 (4 columns)
    __shared__ float4 s[CHUNKS][GROUPS][NP];   // 18 KB

    const int tid = threadIdx.x;
    const int g   = tid & (GROUPS - 1);
    const int cc  = tid >> 6;

    const int t  = blockIdx.x * GROUPS + g;    // global float4-group id
    const int wq = t % WQ;
    const int bh = t / WQ;
    const int h  = bh % H;
    const int b  = bh / H;

    float acc[NP][4];
#pragma unroll
    for (int d = 0; d < NP; d++)
#pragma unroll
        for (int k = 0; k < 4; k++) acc[d][k] = 0.0f;

    const int cs = H * W;
    const size_t base = ((size_t)b * FS + cc * CHP) * cs + (size_t)h * W + (size_t)wq * 4;
    const float* p1 = f1 + base;
    const float* p2 = f2 + base;

    const bool hasL = (wq > 0);
    const bool hasR = (wq < WQ - 1);
    const float4 z4 = make_float4(0.f, 0.f, 0.f, 0.f);

#pragma unroll 4
    for (int c = 0; c < CHP; c++) {
        const float* q1 = p1 + (size_t)c * cs;
        const float* q2 = p2 + (size_t)c * cs;

        // Warm L2 for channel c+PF (~2 bodies ahead). No regs, no L1 path.
        if (c + PF < CHP) {
            l2_prefetch(q1 + (size_t)PF * cs);
            l2_prefetch(q2 + (size_t)PF * cs);
        }

        float4 a = *(const float4*)(q1);
        float4 m = *(const float4*)(q2);
        float4 l = hasL ? *(const float4*)(q2 - 4) : z4;
        float4 r = hasR ? *(const float4*)(q2 + 4) : z4;

        float w12[12] = {l.x, l.y, l.z, l.w,
                         m.x, m.y, m.z, m.w,
                         r.x, r.y, r.z, r.w};
        float av[4] = {a.x, a.y, a.z, a.w};

        // plane d => shift i = d-4; f2 window index = k + 8 - d
#pragma unroll
        for (int d = 0; d < NP; d++) {
#pragma unroll
            for (int k = 0; k < 4; k++) {
                acc[d][k] = fmaf(av[k], w12[k + 8 - d], acc[d][k]);
            }
        }
    }

    // stash partials
#pragma unroll
    for (int d = 0; d < NP; d++) {
        s[cc][g][d] = make_float4(acc[d][0], acc[d][1], acc[d][2], acc[d][3]);
    }
    __syncthreads();

    // reduce 2 chunks + write out: 64 groups x 9 planes = 576 float4 stores
    const float inv = 1.0f / (float)FS;
    for (int item = tid; item < GROUPS * NP; item += BLOCK) {
        const int g2 = item / NP;
        const int d  = item % NP;

        float4 a0 = s[0][g2][d];
        float4 a1 = s[1][g2][d];

        float4 o;
        o.x = (a0.x + a1.x) * inv;
        o.y = (a0.y + a1.y) * inv;
        o.z = (a0.z + a1.z) * inv;
        o.w = (a0.w + a1.w) * inv;

        const int t2  = blockIdx.x * GROUPS + g2;
        const int wq2 = t2 % WQ;
        const int bh2 = t2 / WQ;
        const int h2  = bh2 % H;
        const int b2  = bh2 / H;

        const size_t oidx = (((size_t)b2 * NP + d) * H + h2) * W + (size_t)wq2 * 4;
        *(float4*)(out + oidx) = o;
    }
}

extern "C" void kernel_launch(void* const* d_in, const int* in_sizes, int n_in,
                              void* d_out, int out_size) {
    const float* f1 = (const float*)d_in[0];
    const float* f2 = (const float*)d_in[1];
    float* out = (float*)d_out;

    const int total_groups = BS * H * WQ;          // 61440
    const int grid = total_groups / GROUPS;        // 960 blocks
    cost_volume_kernel<<<grid, BLOCK>>>(f1, f2, out);
}

// round 17
// speedup vs baseline: 1.7920x; 1.2494x over previous
#include <cuda_runtime.h>

// CostVolumeBidirectional: f1,f2 (8,96,96,320) f32 -> out (8,9,96,320) f32
// out[b][d][h][w] = (1/96) * sum_c f1[b][c][h][w] * f2[b][c][h][w-(d-4)]
// zero where w-(d-4) outside [0,320).
//
// R17: minimal delta on the 45.8us champion (R10). Evidence so far: every
// structural rewrite (smem/shfl/cp.async/ping-pong/prefetch) lost to R10's
// ptxas schedule; unroll-2-ish variants hit DRAM 34%, unroll-4 hits 53% ->
// batching depth is the live lever. Changes: (1) unroll 8 (32 batched
// LDG.128 per warp-body, 2x bytes-in-flight per stall episode), (2) reg
// budget 64 -> 73 via __launch_bounds__(128,7) (occupancy is thread-limited
// at ~26 warps/SM, needing only ~6.5 blocks/SM, so 7-block cap costs
// nothing), (3) __ldcs on the f1 load (no reuse -> evict-first, preserve L1
// for f2 halo hits).

#define BS 8
#define FS 96
#define H  96
#define W  320
#define WQ (W / 4)      // 80 float4 groups per row
#define NP 9            // disparity planes

#define GROUPS 64       // float4-groups per block
#define CHUNKS 2        // channel chunks per group
#define CHP (FS / CHUNKS)  // 48 channels per thread
#define BLOCK (GROUPS * CHUNKS)   // 128 threads

__global__ __launch_bounds__(BLOCK, 7)
void cost_volume_kernel(const float* __restrict__ f1,
                        const float* __restrict__ f2,
                        float* __restrict__ out) {
    // partial accumulators: [chunk][group][plane] as float4 (4 columns)
    __shared__ float4 s[CHUNKS][GROUPS][NP];   // 18 KB

    const int tid = threadIdx.x;
    const int g   = tid & (GROUPS - 1);
    const int cc  = tid >> 6;

    const int t  = blockIdx.x * GROUPS + g;    // global float4-group id
    const int wq = t % WQ;
    const int bh = t / WQ;
    const int h  = bh % H;
    const int b  = bh / H;

    float acc[NP][4];
#pragma unroll
    for (int d = 0; d < NP; d++)
#pragma unroll
        for (int k = 0; k < 4; k++) acc[d][k] = 0.0f;

    const int cs = H * W;
    const size_t base = ((size_t)b * FS + cc * CHP) * cs + (size_t)h * W + (size_t)wq * 4;
    const float* p1 = f1 + base;
    const float* p2 = f2 + base;

    const bool hasL = (wq > 0);
    const bool hasR = (wq < WQ - 1);
    const float4 z4 = make_float4(0.f, 0.f, 0.f, 0.f);

#pragma unroll 8
    for (int c = 0; c < CHP; c++) {
        const float* q1 = p1 + (size_t)c * cs;
        const float* q2 = p2 + (size_t)c * cs;

        // f1: no reuse by anyone -> streaming (evict-first), keep L1 for f2
        float4 a = __ldcs((const float4*)(q1));
        float4 m = *(const float4*)(q2);
        float4 l = hasL ? *(const float4*)(q2 - 4) : z4;
        float4 r = hasR ? *(const float4*)(q2 + 4) : z4;

        float w12[12] = {l.x, l.y, l.z, l.w,
                         m.x, m.y, m.z, m.w,
                         r.x, r.y, r.z, r.w};
        float av[4] = {a.x, a.y, a.z, a.w};

        // plane d => shift i = d-4; f2 window index = k + 8 - d
#pragma unroll
        for (int d = 0; d < NP; d++) {
#pragma unroll
            for (int k = 0; k < 4; k++) {
                acc[d][k] = fmaf(av[k], w12[k + 8 - d], acc[d][k]);
            }
        }
    }

    // stash partials
#pragma unroll
    for (int d = 0; d < NP; d++) {
        s[cc][g][d] = make_float4(acc[d][0], acc[d][1], acc[d][2], acc[d][3]);
    }
    __syncthreads();

    // reduce 2 chunks + write out: 64 groups x 9 planes = 576 float4 stores
    const float inv = 1.0f / (float)FS;
    for (int item = tid; item < GROUPS * NP; item += BLOCK) {
        const int g2 = item / NP;
        const int d  = item % NP;

        float4 a0 = s[0][g2][d];
        float4 a1 = s[1][g2][d];

        float4 o;
        o.x = (a0.x + a1.x) * inv;
        o.y = (a0.y + a1.y) * inv;
        o.z = (a0.z + a1.z) * inv;
        o.w = (a0.w + a1.w) * inv;

        const int t2  = blockIdx.x * GROUPS + g2;
        const int wq2 = t2 % WQ;
        const int bh2 = t2 / WQ;
        const int h2  = bh2 % H;
        const int b2  = bh2 / H;

        const size_t oidx = (((size_t)b2 * NP + d) * H + h2) * W + (size_t)wq2 * 4;
        *(float4*)(out + oidx) = o;
    }
}

extern "C" void kernel_launch(void* const* d_in, const int* in_sizes, int n_in,
                              void* d_out, int out_size) {
    const float* f1 = (const float*)d_in[0];
    const float* f2 = (const float*)d_in[1];
    float* out = (float*)d_out;

    const int total_groups = BS * H * WQ;          // 61440
    const int grid = total_groups / GROUPS;        // 960 blocks
    cost_volume_kernel<<<grid, BLOCK>>>(f1, f2, out);
}